// round 14
// baseline (speedup 1.0000x reference)
#include <cuda_runtime.h>
#include <cuda_fp16.h>

// CEHawkesProcess — Hawkes NLL. SINGLE launch: cooperative fp16-table prep +
// soft grid barrier (volatile spin + nanosleep) + paired-event main phase.
// Grid = 716 blocks, __launch_bounds__(256,5) -> >=740 co-resident slots, so
// the barrier cannot deadlock. Event pairs (i, 255-i) share one history load
// with both events' td pre-baked as half2; two sequential accumulate passes.
// Inputs (metadata order):
// 0 event_times f32[B*L], 1 event_types i32[B*L], 2 event_categories i32[B*L],
// 3 T (scalar), 4 type_emb f32[NT*E], 5 cat_emb f32[NC*E], 6 a f32[NT*E],
// 7 b f32[NC*E], 8 A f32[NT*NT*E], 9 P f32[NT*NT*E], 10 Bm f32[NC*NC*E],
// 11 Q f32[NC*NC*E].  Output: scalar f32.

namespace {
constexpr int NTY = 50;
constexpr int NCA = 20;
constexpr int EMB = 64;
constexpr int LP = EMB / 2;                 // lane-pairs per row = 32
constexpr int BSZ = 4;
constexpr int SEQ = 256;
constexpr float NL2E = -1.4426950408889634f;  // -log2(e)

constexpr int EVP_BLKS = BSZ * (SEQ / 2);                 // 512 (event pairs)
constexpr int HT_BLKS = BSZ * NTY;                        // 200
constexpr int HC_BLKS = BSZ;                              // 4
constexpr int MAIN_BLKS = EVP_BLKS + HT_BLKS + HC_BLKS;   // 716 <= 740

constexpr int TT_ROWS = NTY * NTY;                        // 2500
constexpr int TAB_ROWS = TT_ROWS + NCA * NCA;             // 2900; 5 rows/blk -> 580
}

// Tables, [target][source][lanepair]: uint2 = {half2{w_e0,w_e1}, half2{r_e0,r_e1}}.
__device__ uint2 g_TT2[NTY * NTY * LP];
__device__ uint2 g_TC2[NCA * NCA * LP];
__device__ float g_FEmb[NTY * EMB];
__device__ float g_BA[NTY];
__device__ float g_SP[NTY];
__device__ float g_FB[NTY * NCA];
__device__ float g_Fsum[EMB];
__device__ float g_SFB[NCA];
__device__ float g_Sba, g_I0;
__device__ float g_part[MAIN_BLKS];
__device__ unsigned g_ready;               // prep barrier (finalizer resets)
__device__ unsigned g_done;                // completion counter (finalizer resets)

struct alignas(16) Ent { unsigned tdL; unsigned tdH; int ko; int co; };

__device__ __forceinline__ __half2 fast_exp2_h2(__half2 x) {
    unsigned xi = *(unsigned*)&x;
    unsigned r;
    asm("ex2.approx.f16x2 %0, %1;" : "=r"(r) : "r"(xi));
    return *(__half2*)&r;
}

__device__ __forceinline__ float softplusf(float x) {
    return fmaxf(x, 0.f) + log1pf(expf(-fabsf(x)));
}

// T may arrive as int32 (value 128) or float32 bits; disambiguate.
__device__ __forceinline__ float readT(const void* p) {
    int v = *(const int*)p;
    return (v > 0 && v < (1 << 24)) ? (float)v : __int_as_float(v);
}

__device__ __forceinline__ float warp_reduce(float v) {
    #pragma unroll
    for (int o = 16; o; o >>= 1) v += __shfl_down_sync(0xffffffffu, v, o);
    return v;
}

__device__ __forceinline__ float block_reduce_256(float v, float* sred) {
    v = warp_reduce(v);
    int tid = threadIdx.x;
    if ((tid & 31) == 0) sred[tid >> 5] = v;
    __syncthreads();
    float r = 0.f;
    if (tid == 0) {
        #pragma unroll
        for (int w = 0; w < 8; w++) r += sred[w];
    }
    return r;
}

__device__ __forceinline__ unsigned td_to_h2(float td) {
    __half h = __float2half_rn(td);
    __half2 h2 = __half2half2(h);
    return *(unsigned*)&h2;
}

__global__ void __launch_bounds__(256, 5) k_all(
    const float* __restrict__ times, const int* __restrict__ types,
    const int* __restrict__ cats, const void* __restrict__ Tp,
    const float* __restrict__ f, const float* __restrict__ g,
    const float* __restrict__ a, const float* __restrict__ b,
    const float* __restrict__ A, const float* __restrict__ P,
    const float* __restrict__ Bm, const float* __restrict__ Q,
    float* __restrict__ out) {
    int bid = blockIdx.x;
    int tid = threadIdx.x;
    __shared__ Ent sh[SEQ];              // 4KB; reused as float scratch in prep
    __shared__ float sredA[8];
    __shared__ float sredB[8];
    __shared__ double dred[8];
    __shared__ int sh_last;

    // ===================== phase 1: cooperative prep ==========================
    {
        // Table rows: 5 per block across blocks 0..579. Each row: 32 lane-pairs.
        int el = tid & 63;
        #pragma unroll
        for (int j = 0; j < 2; j++) {
            int sub = j * 4 + (tid >> 6);
            if (sub < 5 && el < 32) {
                int row = bid * 5 + sub;
                int e0 = el * 2, e1 = e0 + 1;
                if (row < TT_ROWS) {
                    int t = row / NTY, k = row - t * NTY;
                    int rd0 = (k * NTY + t) * EMB + e0;   // A/P stored [k][t][e]
                    float w0 = f[t * EMB + e0] * f[k * EMB + e0];
                    float w1 = f[t * EMB + e1] * f[k * EMB + e1];
                    __half2 hw = __floats2half2_rn(w0 * __ldg(A + rd0),
                                                   w1 * __ldg(A + rd0 + 1));
                    __half2 hr = __floats2half2_rn(NL2E * w0 * __ldg(P + rd0),
                                                   NL2E * w1 * __ldg(P + rd0 + 1));
                    uint2 pkt;
                    pkt.x = *(unsigned*)&hw;
                    pkt.y = *(unsigned*)&hr;
                    g_TT2[row * LP + el] = pkt;
                } else if (row < TAB_ROWS) {
                    int p2 = row - TT_ROWS;               // c2*NCA + c1
                    int c2 = p2 / NCA, c1 = p2 - c2 * NCA;
                    int rd0 = (c1 * NCA + c2) * EMB + e0; // Bm/Q stored [c1][c2][e]
                    float w0 = g[c2 * EMB + e0] * g[c1 * EMB + e0];
                    float w1 = g[c2 * EMB + e1] * g[c1 * EMB + e1];
                    __half2 hw = __floats2half2_rn(w0 * __ldg(Bm + rd0),
                                                   w1 * __ldg(Bm + rd0 + 1));
                    __half2 hr = __floats2half2_rn(NL2E * w0 * __ldg(Q + rd0),
                                                   NL2E * w1 * __ldg(Q + rd0 + 1));
                    uint2 pkt;
                    pkt.x = *(unsigned*)&hw;
                    pkt.y = *(unsigned*)&hr;
                    g_TC2[p2 * LP + el] = pkt;
                }
            }
        }
        if (bid >= 580 && bid < 612) {
            // FB dots: 32 per block (warp per dot)
            int w = tid >> 5, lane = tid & 31;
            int base = (bid - 580) * 32;
            for (int q = w; q < 32; q += 8) {
                int idx = base + q;
                if (idx < NTY * NCA) {
                    int t = idx / NCA, c = idx - t * NCA;
                    float s = f[t * EMB + lane] * b[c * EMB + lane]
                            + f[t * EMB + lane + 32] * b[c * EMB + lane + 32];
                    s = warp_reduce(s);
                    if (lane == 0) g_FB[idx] = s;
                }
            }
        } else if (bid == 612) {
            int w = tid >> 5, lane = tid & 31;
            for (int t = w; t < NTY; t += 8) {
                float x0 = f[t * EMB + lane] * a[t * EMB + lane];
                float x1 = f[t * EMB + lane + 32] * a[t * EMB + lane + 32];
                float ba = warp_reduce(x0 + x1);
                float sp = warp_reduce(softplusf(x0) + softplusf(x1));
                if (lane == 0) { g_BA[t] = ba; g_SP[t] = sp; }
            }
        } else if (bid == 613) {
            for (int idx = tid; idx < NTY * EMB; idx += 256) g_FEmb[idx] = f[idx];
        } else if (bid == 614) {
            float* fs_sh = (float*)sh;
            if (tid < EMB) {
                float s = 0.f;
                #pragma unroll
                for (int t = 0; t < NTY; t++) s += f[t * EMB + tid];
                g_Fsum[tid] = s;
                fs_sh[tid] = s;
            }
            float sba = 0.f, i0 = 0.f;
            for (int idx = tid; idx < NTY * EMB; idx += 256) {
                float x = f[idx] * a[idx];
                sba += x;
                i0 += softplusf(x);
            }
            sba = warp_reduce(sba);
            i0 = warp_reduce(i0);
            if ((tid & 31) == 0) { sredA[tid >> 5] = sba; sredB[tid >> 5] = i0; }
            __syncthreads();
            if (tid == 0) {
                float s = 0.f, s2 = 0.f;
                #pragma unroll
                for (int w = 0; w < 8; w++) { s += sredA[w]; s2 += sredB[w]; }
                g_Sba = s;
                g_I0 = s2;
            }
            int w = tid >> 5, lane = tid & 31;
            for (int c = w; c < NCA; c += 8) {
                float s = fs_sh[lane] * b[c * EMB + lane]
                        + fs_sh[lane + 32] * b[c * EMB + lane + 32];
                s = warp_reduce(s);
                if (lane == 0) g_SFB[c] = s;
            }
        }
        // ---- grid barrier: arrive once, spin on volatile load with backoff ----
        __syncthreads();
        if (tid == 0) {
            __threadfence();
            atomicAdd(&g_ready, 1u);
            while (*(volatile unsigned*)&g_ready < (unsigned)MAIN_BLKS)
                __nanosleep(128);
        }
        __syncthreads();
    }

    // ===================== phase 2: main math =================================
    int lane = tid & 31;
    int ch = tid >> 5;          // 0..7 chunks; one warp covers all 64 e per item
    float partial = 0.f;
    const __half2 hz = __float2half2_rn(0.f);

    if (bid < EVP_BLKS) {
        // ---- event pair (i_hi = 255-p, i_lo = p); shared history load ----
        int bb = bid & 3;
        int p = bid >> 2;
        int i_hi = (SEQ - 1) - p;
        int i_lo = p;
        const float* ts = times + bb * SEQ;
        const int* ty = types + bb * SEQ;
        const int* ct = cats + bb * SEQ;
        float tH = ts[i_hi];
        float tL = ts[i_lo];

        for (int s = tid; s < i_hi; s += 256) {
            float t_s = ts[s];
            Ent en;
            en.tdL = td_to_h2(tL - t_s);
            en.tdH = td_to_h2(tH - t_s);
            en.ko = ty[s] * LP;
            en.co = ct[s] * LP;
            sh[s] = en;
        }
        __syncthreads();

        // ---- pass A: event i_hi ----
        {
            int ti = ty[i_hi];
            int lc = ct[i_hi - 1];
            const uint2* __restrict__ ttb = g_TT2 + (size_t)ti * (NTY * LP) + lane;
            const uint2* __restrict__ tcb = g_TC2 + (size_t)lc * (NCA * LP) + lane;
            __half2 aT0 = hz, aT1 = hz, aC0 = hz, aC1 = hz;
            int s = ch;
            for (; s + 8 < i_hi; s += 16) {
                Ent e0 = sh[s], e1 = sh[s + 8];
                uint2 t0 = __ldg(ttb + e0.ko);
                uint2 c0 = __ldg(tcb + e0.co);
                uint2 t1 = __ldg(ttb + e1.ko);
                uint2 c1 = __ldg(tcb + e1.co);
                __half2 td0 = *(__half2*)&e0.tdH;
                __half2 td1 = *(__half2*)&e1.tdH;
                aT0 = __hfma2(*(__half2*)&t0.x, fast_exp2_h2(__hmul2(*(__half2*)&t0.y, td0)), aT0);
                aC0 = __hfma2(*(__half2*)&c0.x, fast_exp2_h2(__hmul2(*(__half2*)&c0.y, td0)), aC0);
                aT1 = __hfma2(*(__half2*)&t1.x, fast_exp2_h2(__hmul2(*(__half2*)&t1.y, td1)), aT1);
                aC1 = __hfma2(*(__half2*)&c1.x, fast_exp2_h2(__hmul2(*(__half2*)&c1.y, td1)), aC1);
            }
            if (s < i_hi) {
                Ent e0 = sh[s];
                uint2 t0 = __ldg(ttb + e0.ko);
                uint2 c0 = __ldg(tcb + e0.co);
                __half2 td0 = *(__half2*)&e0.tdH;
                aT0 = __hfma2(*(__half2*)&t0.x, fast_exp2_h2(__hmul2(*(__half2*)&t0.y, td0)), aT0);
                aC0 = __hfma2(*(__half2*)&c0.x, fast_exp2_h2(__hmul2(*(__half2*)&c0.y, td0)), aC0);
            }
            float2 fT0 = __half22float2(aT0);
            float2 fT1 = __half22float2(aT1);
            float2 fC0 = __half22float2(aC0);
            float2 fC1 = __half22float2(aC1);
            float2 fev = *(const float2*)(g_FEmb + ti * EMB + lane * 2);
            float acc = (fT0.x + fT1.x) + fev.x * (fC0.x + fC1.x)
                      + (fT0.y + fT1.y) + fev.y * (fC0.y + fC1.y);
            float total = block_reduce_256(acc, sredA);
            if (tid == 0 && tH >= 0.f) {
                float lam = g_BA[ti] + g_FB[ti * NCA + lc] + total;
                partial = -(logf(lam + 1e-16f) + lam);
            }
        }
        // ---- pass B: event i_lo ----
        if (i_lo == 0) {
            if (tid == 0 && tL >= 0.f) {
                float lam = g_SP[ty[0]];
                partial += -(logf(lam + 1e-16f) + lam);
            }
        } else {
            int ti = ty[i_lo];
            int lc = ct[i_lo - 1];
            const uint2* __restrict__ ttb = g_TT2 + (size_t)ti * (NTY * LP) + lane;
            const uint2* __restrict__ tcb = g_TC2 + (size_t)lc * (NCA * LP) + lane;
            __half2 aT0 = hz, aT1 = hz, aC0 = hz, aC1 = hz;
            int s = ch;
            for (; s + 8 < i_lo; s += 16) {
                Ent e0 = sh[s], e1 = sh[s + 8];
                uint2 t0 = __ldg(ttb + e0.ko);
                uint2 c0 = __ldg(tcb + e0.co);
                uint2 t1 = __ldg(ttb + e1.ko);
                uint2 c1 = __ldg(tcb + e1.co);
                __half2 td0 = *(__half2*)&e0.tdL;
                __half2 td1 = *(__half2*)&e1.tdL;
                aT0 = __hfma2(*(__half2*)&t0.x, fast_exp2_h2(__hmul2(*(__half2*)&t0.y, td0)), aT0);
                aC0 = __hfma2(*(__half2*)&c0.x, fast_exp2_h2(__hmul2(*(__half2*)&c0.y, td0)), aC0);
                aT1 = __hfma2(*(__half2*)&t1.x, fast_exp2_h2(__hmul2(*(__half2*)&t1.y, td1)), aT1);
                aC1 = __hfma2(*(__half2*)&c1.x, fast_exp2_h2(__hmul2(*(__half2*)&c1.y, td1)), aC1);
            }
            if (s < i_lo) {
                Ent e0 = sh[s];
                uint2 t0 = __ldg(ttb + e0.ko);
                uint2 c0 = __ldg(tcb + e0.co);
                __half2 td0 = *(__half2*)&e0.tdL;
                aT0 = __hfma2(*(__half2*)&t0.x, fast_exp2_h2(__hmul2(*(__half2*)&t0.y, td0)), aT0);
                aC0 = __hfma2(*(__half2*)&c0.x, fast_exp2_h2(__hmul2(*(__half2*)&c0.y, td0)), aC0);
            }
            float2 fT0 = __half22float2(aT0);
            float2 fT1 = __half22float2(aT1);
            float2 fC0 = __half22float2(aC0);
            float2 fC1 = __half22float2(aC1);
            float2 fev = *(const float2*)(g_FEmb + ti * EMB + lane * 2);
            float acc = (fT0.x + fT1.x) + fev.x * (fC0.x + fC1.x)
                      + (fT0.y + fT1.y) + fev.y * (fC0.y + fC1.y);
            float total = block_reduce_256(acc, sredB);
            if (tid == 0 && tL >= 0.f) {
                float lam = g_BA[ti] + g_FB[ti * NCA + lc] + total;
                partial += -(logf(lam + 1e-16f) + lam);
            }
        }
    } else if (bid < EVP_BLKS + HT_BLKS) {
        // ---- horizon type channel: (b, t) ----
        int idx0 = bid - EVP_BLKS;
        int bb = idx0 / NTY;
        int t = idx0 - bb * NTY;
        float Tf = readT(Tp);
        const float* ts = times + bb * SEQ;
        const int* ty = types + bb * SEQ;
        float tlast = ts[SEQ - 1];
        for (int s = tid; s < SEQ; s += 256) {
            Ent en; en.tdH = td_to_h2(Tf - ts[s]); en.tdL = 0;
            en.ko = ty[s] * LP; en.co = 0;
            sh[s] = en;
        }
        __syncthreads();
        const uint2* __restrict__ ttb = g_TT2 + (size_t)t * (NTY * LP) + lane;
        __half2 a0 = hz, a1 = hz;
        #pragma unroll 2
        for (int s = ch; s < SEQ; s += 16) {
            Ent e0 = sh[s], e1 = sh[s + 8];
            uint2 r0 = __ldg(ttb + e0.ko);
            uint2 r1 = __ldg(ttb + e1.ko);
            a0 = __hfma2(*(__half2*)&r0.x,
                         fast_exp2_h2(__hmul2(*(__half2*)&r0.y, *(__half2*)&e0.tdH)), a0);
            a1 = __hfma2(*(__half2*)&r1.x,
                         fast_exp2_h2(__hmul2(*(__half2*)&r1.y, *(__half2*)&e1.tdH)), a1);
        }
        float2 f0 = __half22float2(a0);
        float2 f1 = __half22float2(a1);
        float total = block_reduce_256((f0.x + f0.y) + (f1.x + f1.y), sredA);
        if (tid == 0) partial = total * (readT(Tp) - tlast);
    } else {
        // ---- horizon category channel: b ----
        int bb = bid - EVP_BLKS - HT_BLKS;
        float Tf = readT(Tp);
        const float* ts = times + bb * SEQ;
        const int* ct = cats + bb * SEQ;
        float tlast = ts[SEQ - 1];
        for (int s = tid; s < SEQ; s += 256) {
            Ent en; en.tdH = td_to_h2(Tf - ts[s]); en.tdL = 0;
            en.co = ct[s] * LP; en.ko = 0;
            sh[s] = en;
        }
        __syncthreads();
        int lcL = ct[SEQ - 1];
        const uint2* __restrict__ tcb = g_TC2 + (size_t)lcL * (NCA * LP) + lane;
        __half2 a0 = hz, a1 = hz;
        #pragma unroll 2
        for (int s = ch; s < SEQ; s += 16) {
            Ent e0 = sh[s], e1 = sh[s + 8];
            uint2 r0 = __ldg(tcb + e0.co);
            uint2 r1 = __ldg(tcb + e1.co);
            a0 = __hfma2(*(__half2*)&r0.x,
                         fast_exp2_h2(__hmul2(*(__half2*)&r0.y, *(__half2*)&e0.tdH)), a0);
            a1 = __hfma2(*(__half2*)&r1.x,
                         fast_exp2_h2(__hmul2(*(__half2*)&r1.y, *(__half2*)&e1.tdH)), a1);
        }
        float2 f0 = __half22float2(a0);
        float2 f1 = __half22float2(a1);
        float2 fsum = *(const float2*)(g_Fsum + lane * 2);
        float acc = (f0.x + f1.x) * fsum.x + (f0.y + f1.y) * fsum.y;
        float total = block_reduce_256(acc, sredA);
        if (tid == 0) partial = total * (Tf - tlast);
    }

    // ===================== phase 3: publish + finalizer =======================
    if (tid == 0) {
        g_part[bid] = partial;
        __threadfence();
        unsigned n = atomicAdd(&g_done, 1u);
        sh_last = (n == (unsigned)(MAIN_BLKS - 1)) ? 1 : 0;
        if (sh_last) __threadfence();
    }
    __syncthreads();
    if (sh_last) {
        double v = 0.0;
        for (int idx = tid; idx < MAIN_BLKS; idx += 256) v += (double)g_part[idx];
        #pragma unroll
        for (int o = 16; o; o >>= 1) v += __shfl_down_sync(0xffffffffu, v, o);
        if ((tid & 31) == 0) dred[tid >> 5] = v;
        __syncthreads();
        if (tid == 0) {
            double r = 0.0;
            #pragma unroll
            for (int w = 0; w < 8; w++) r += dred[w];
            float Tf = readT(Tp);
            for (int b2 = 0; b2 < BSZ; b2++) {
                int lcL = cats[b2 * SEQ + SEQ - 1];
                float tlast = times[b2 * SEQ + SEQ - 1];
                float t0 = times[b2 * SEQ];
                r += (double)((g_Sba + g_SFB[lcL]) * (Tf - tlast) + g_I0 * t0);
            }
            out[0] = (float)r;
            g_done = 0u;   // reset for next replay
            g_ready = 0u;
        }
    }
}

extern "C" void kernel_launch(void* const* d_in, const int* in_sizes, int n_in,
                              void* d_out, int out_size) {
    const float* times = (const float*)d_in[0];
    const int* types = (const int*)d_in[1];
    const int* cats = (const int*)d_in[2];
    const void* Tp = d_in[3];
    const float* type_emb = (const float*)d_in[4];
    const float* cat_emb = (const float*)d_in[5];
    const float* a = (const float*)d_in[6];
    const float* b = (const float*)d_in[7];
    const float* A = (const float*)d_in[8];
    const float* P = (const float*)d_in[9];
    const float* Bm = (const float*)d_in[10];
    const float* Q = (const float*)d_in[11];
    float* out = (float*)d_out;

    k_all<<<MAIN_BLKS, 256>>>(times, types, cats, Tp, type_emb, cat_emb,
                              a, b, A, P, Bm, Q, out);
}

// round 15
// speedup vs baseline: 1.0845x; 1.0845x over previous
#include <cuda_runtime.h>
#include <cuda_fp16.h>

// CEHawkesProcess — Hawkes NLL. 2 launches: parallel prep + paired-event main.
// f16x2 exp pipeline (HMUL2 -> ex2.approx.f16x2 -> HFMA2, one MUFU op per 2 e's).
// Event pairs (i, 255-i) share one history load; both tds pre-baked as half2.
// Inputs (metadata order):
// 0 event_times f32[B*L], 1 event_types i32[B*L], 2 event_categories i32[B*L],
// 3 T (scalar), 4 type_emb f32[NT*E], 5 cat_emb f32[NC*E], 6 a f32[NT*E],
// 7 b f32[NC*E], 8 A f32[NT*NT*E], 9 P f32[NT*NT*E], 10 Bm f32[NC*NC*E],
// 11 Q f32[NC*NC*E].  Output: scalar f32.

namespace {
constexpr int NTY = 50;
constexpr int NCA = 20;
constexpr int EMB = 64;
constexpr int LP = EMB / 2;                 // lane-pairs per row = 32
constexpr int BSZ = 4;
constexpr int SEQ = 256;
constexpr float NL2E = -1.4426950408889634f;  // -log2(e)

constexpr int EVP_BLKS = BSZ * (SEQ / 2);                 // 512 (event pairs)
constexpr int HT_BLKS = BSZ * NTY;                        // 200
constexpr int HC_BLKS = BSZ;                              // 4
constexpr int MAIN_BLKS = EVP_BLKS + HT_BLKS + HC_BLKS;   // 716

constexpr int TT_BLKS = (NTY * NTY + 15) / 16;            // 157
constexpr int TC_BLKS = (NCA * NCA + 15) / 16;            // 25
constexpr int FB_BLKS = (NTY * NCA + 7) / 8;              // 125
constexpr int BA_BLKS = (NTY + 7) / 8;                    // 7
constexpr int FE_BLKS = 4;
constexpr int PREP_BLKS = TT_BLKS + TC_BLKS + FB_BLKS + BA_BLKS + FE_BLKS + 1;  // 319
}

// Tables, [target][source][lanepair]: uint2 = {half2{w_e0,w_e1}, half2{r_e0,r_e1}}.
__device__ uint2 g_TT2[NTY * NTY * LP];
__device__ uint2 g_TC2[NCA * NCA * LP];
__device__ float g_FEmb[NTY * EMB];
__device__ float g_BA[NTY];
__device__ float g_SP[NTY];
__device__ float g_FB[NTY * NCA];
__device__ float g_Fsum[EMB];
__device__ float g_SFB[NCA];
__device__ float g_Sba, g_I0;
__device__ float g_part[MAIN_BLKS];
__device__ unsigned g_done;                // zero-init; finalizer resets (replay-safe)

struct alignas(16) Ent { unsigned tdL; unsigned tdH; int ko; int co; };

__device__ __forceinline__ __half2 fast_exp2_h2(__half2 x) {
    unsigned xi = *(unsigned*)&x;
    unsigned r;
    asm("ex2.approx.f16x2 %0, %1;" : "=r"(r) : "r"(xi));
    return *(__half2*)&r;
}

__device__ __forceinline__ float softplusf(float x) {
    return fmaxf(x, 0.f) + log1pf(expf(-fabsf(x)));
}

// T may arrive as int32 (value 128) or float32 bits; disambiguate.
__device__ __forceinline__ float readT(const void* p) {
    int v = *(const int*)p;
    return (v > 0 && v < (1 << 24)) ? (float)v : __int_as_float(v);
}

__device__ __forceinline__ float warp_reduce(float v) {
    #pragma unroll
    for (int o = 16; o; o >>= 1) v += __shfl_down_sync(0xffffffffu, v, o);
    return v;
}

__device__ __forceinline__ float block_reduce_256(float v, float* sred) {
    v = warp_reduce(v);
    int tid = threadIdx.x;
    if ((tid & 31) == 0) sred[tid >> 5] = v;
    __syncthreads();
    float r = 0.f;
    if (tid == 0) {
        #pragma unroll
        for (int w = 0; w < 8; w++) r += sred[w];
    }
    return r;
}

__device__ __forceinline__ unsigned td_to_h2(float td) {
    __half h = __float2half_rn(td);
    __half2 h2 = __half2half2(h);
    return *(unsigned*)&h2;
}

// ======================= prep: tables + scalars + femb, all parallel =========
__global__ void __launch_bounds__(256) k_prep(
    const float* __restrict__ f, const float* __restrict__ g,
    const float* __restrict__ a, const float* __restrict__ b,
    const float* __restrict__ A, const float* __restrict__ P,
    const float* __restrict__ Bm, const float* __restrict__ Q) {
    int bid = blockIdx.x;
    int tid = threadIdx.x;

    if (bid < TT_BLKS) {
        int p = bid * 16 + (tid >> 4);          // p = t*NTY + k (write row)
        if (p < NTY * NTY) {
            int e = (tid & 15) << 2;            // e..e+3
            int t = p / NTY, k = p - t * NTY;
            int rd = (k * NTY + t) * EMB + e;   // A/P stored [k][t][e]
            float4 Av = *(const float4*)(A + rd);
            float4 Pv = *(const float4*)(P + rd);
            float4 ft = *(const float4*)(f + t * EMB + e);
            float4 fk = *(const float4*)(f + k * EMB + e);
            float w0 = ft.x * fk.x, w1 = ft.y * fk.y;
            float w2 = ft.z * fk.z, w3 = ft.w * fk.w;
            __half2 hw01 = __floats2half2_rn(w0 * Av.x, w1 * Av.y);
            __half2 hr01 = __floats2half2_rn(NL2E * w0 * Pv.x, NL2E * w1 * Pv.y);
            __half2 hw23 = __floats2half2_rn(w2 * Av.z, w3 * Av.w);
            __half2 hr23 = __floats2half2_rn(NL2E * w2 * Pv.z, NL2E * w3 * Pv.w);
            uint4 pkt;
            pkt.x = *(unsigned*)&hw01; pkt.y = *(unsigned*)&hr01;
            pkt.z = *(unsigned*)&hw23; pkt.w = *(unsigned*)&hr23;
            *(uint4*)(g_TT2 + p * LP + (e >> 1)) = pkt;
        }
        return;
    }
    bid -= TT_BLKS;
    if (bid < TC_BLKS) {
        int p = bid * 16 + (tid >> 4);          // p = c2*NCA + c1 (write row)
        if (p < NCA * NCA) {
            int e = (tid & 15) << 2;
            int c2 = p / NCA, c1 = p - c2 * NCA;
            int rd = (c1 * NCA + c2) * EMB + e; // Bm/Q stored [c1][c2][e]
            float4 Bv = *(const float4*)(Bm + rd);
            float4 Qv = *(const float4*)(Q + rd);
            float4 g2 = *(const float4*)(g + c2 * EMB + e);
            float4 g1 = *(const float4*)(g + c1 * EMB + e);
            float w0 = g2.x * g1.x, w1 = g2.y * g1.y;
            float w2 = g2.z * g1.z, w3 = g2.w * g1.w;
            __half2 hw01 = __floats2half2_rn(w0 * Bv.x, w1 * Bv.y);
            __half2 hr01 = __floats2half2_rn(NL2E * w0 * Qv.x, NL2E * w1 * Qv.y);
            __half2 hw23 = __floats2half2_rn(w2 * Bv.z, w3 * Bv.w);
            __half2 hr23 = __floats2half2_rn(NL2E * w2 * Qv.z, NL2E * w3 * Qv.w);
            uint4 pkt;
            pkt.x = *(unsigned*)&hw01; pkt.y = *(unsigned*)&hr01;
            pkt.z = *(unsigned*)&hw23; pkt.w = *(unsigned*)&hr23;
            *(uint4*)(g_TC2 + p * LP + (e >> 1)) = pkt;
        }
        return;
    }
    bid -= TC_BLKS;
    if (bid < FB_BLKS) {
        int w = tid >> 5, lane = tid & 31;
        int idx = bid * 8 + w;
        if (idx < NTY * NCA) {
            int t = idx / NCA, c = idx - t * NCA;
            float s = f[t * EMB + lane] * b[c * EMB + lane]
                    + f[t * EMB + lane + 32] * b[c * EMB + lane + 32];
            s = warp_reduce(s);
            if (lane == 0) g_FB[idx] = s;
        }
        return;
    }
    bid -= FB_BLKS;
    if (bid < BA_BLKS) {
        int w = tid >> 5, lane = tid & 31;
        int t = bid * 8 + w;
        if (t < NTY) {
            float x0 = f[t * EMB + lane] * a[t * EMB + lane];
            float x1 = f[t * EMB + lane + 32] * a[t * EMB + lane + 32];
            float ba = warp_reduce(x0 + x1);
            float sp = warp_reduce(softplusf(x0) + softplusf(x1));
            if (lane == 0) { g_BA[t] = ba; g_SP[t] = sp; }
        }
        return;
    }
    bid -= BA_BLKS;
    if (bid < FE_BLKS) {
        int idx4 = bid * 256 + tid;
        if (idx4 < (NTY * EMB) / 4)
            ((float4*)g_FEmb)[idx4] = ((const float4*)f)[idx4];
        return;
    }
    // ---- final scalar block: Fsum, SFB, Sba, I0 ----
    __shared__ float fs_sh[EMB];
    __shared__ float sred1[8];
    __shared__ float sred2[8];
    if (tid < EMB) {
        float s = 0.f;
        #pragma unroll
        for (int t = 0; t < NTY; t++) s += f[t * EMB + tid];
        g_Fsum[tid] = s;
        fs_sh[tid] = s;
    }
    float sba = 0.f, i0 = 0.f;
    for (int idx = tid; idx < NTY * EMB; idx += 256) {
        float x = f[idx] * a[idx];
        sba += x;
        i0 += softplusf(x);
    }
    sba = warp_reduce(sba);
    i0 = warp_reduce(i0);
    if ((tid & 31) == 0) { sred1[tid >> 5] = sba; sred2[tid >> 5] = i0; }
    __syncthreads();
    if (tid == 0) {
        float s = 0.f, s2 = 0.f;
        #pragma unroll
        for (int w = 0; w < 8; w++) { s += sred1[w]; s2 += sred2[w]; }
        g_Sba = s;
        g_I0 = s2;
    }
    {
        int w = tid >> 5, lane = tid & 31;
        for (int c = w; c < NCA; c += 8) {
            float s = fs_sh[lane] * b[c * EMB + lane]
                    + fs_sh[lane + 32] * b[c * EMB + lane + 32];
            s = warp_reduce(s);
            if (lane == 0) g_SFB[c] = s;
        }
    }
}

// ======================= main: paired events, f16x2 pipeline =================
__global__ void __launch_bounds__(256) k_main(
    const float* __restrict__ times, const int* __restrict__ types,
    const int* __restrict__ cats, const void* __restrict__ Tp,
    float* __restrict__ out) {
    int bid = blockIdx.x;
    int tid = threadIdx.x;
    __shared__ Ent sh[SEQ];
    __shared__ float sredA[8];
    __shared__ float sredB[8];
    __shared__ double dred[8];
    __shared__ int sh_last;

    int lane = tid & 31;
    int ch = tid >> 5;          // 0..7 chunks; one warp covers all 64 e per item
    float partial = 0.f;
    const __half2 hz = __float2half2_rn(0.f);

    if (bid < EVP_BLKS) {
        // ---- event pair (i_hi = 255-p, i_lo = p); one shared history load ----
        int bb = bid & 3;
        int p = bid >> 2;
        int i_hi = (SEQ - 1) - p;
        int i_lo = p;
        const float* ts = times + bb * SEQ;
        const int* ty = types + bb * SEQ;
        const int* ct = cats + bb * SEQ;
        float tH = ts[i_hi];
        float tL = ts[i_lo];

        for (int s = tid; s < i_hi; s += 256) {
            float t_s = ts[s];
            Ent en;
            en.tdL = td_to_h2(tL - t_s);
            en.tdH = td_to_h2(tH - t_s);
            en.ko = ty[s] * LP;
            en.co = ct[s] * LP;
            sh[s] = en;
        }
        __syncthreads();

        // ---- pass A: event i_hi ----
        {
            int ti = ty[i_hi];
            int lc = ct[i_hi - 1];
            const uint2* __restrict__ ttb = g_TT2 + (size_t)ti * (NTY * LP) + lane;
            const uint2* __restrict__ tcb = g_TC2 + (size_t)lc * (NCA * LP) + lane;
            __half2 aT0 = hz, aT1 = hz, aC0 = hz, aC1 = hz;
            int s = ch;
            for (; s + 8 < i_hi; s += 16) {
                Ent e0 = sh[s], e1 = sh[s + 8];
                uint2 t0 = __ldg(ttb + e0.ko);
                uint2 c0 = __ldg(tcb + e0.co);
                uint2 t1 = __ldg(ttb + e1.ko);
                uint2 c1 = __ldg(tcb + e1.co);
                __half2 td0 = *(__half2*)&e0.tdH;
                __half2 td1 = *(__half2*)&e1.tdH;
                aT0 = __hfma2(*(__half2*)&t0.x, fast_exp2_h2(__hmul2(*(__half2*)&t0.y, td0)), aT0);
                aC0 = __hfma2(*(__half2*)&c0.x, fast_exp2_h2(__hmul2(*(__half2*)&c0.y, td0)), aC0);
                aT1 = __hfma2(*(__half2*)&t1.x, fast_exp2_h2(__hmul2(*(__half2*)&t1.y, td1)), aT1);
                aC1 = __hfma2(*(__half2*)&c1.x, fast_exp2_h2(__hmul2(*(__half2*)&c1.y, td1)), aC1);
            }
            if (s < i_hi) {
                Ent e0 = sh[s];
                uint2 t0 = __ldg(ttb + e0.ko);
                uint2 c0 = __ldg(tcb + e0.co);
                __half2 td0 = *(__half2*)&e0.tdH;
                aT0 = __hfma2(*(__half2*)&t0.x, fast_exp2_h2(__hmul2(*(__half2*)&t0.y, td0)), aT0);
                aC0 = __hfma2(*(__half2*)&c0.x, fast_exp2_h2(__hmul2(*(__half2*)&c0.y, td0)), aC0);
            }
            float2 fT0 = __half22float2(aT0);
            float2 fT1 = __half22float2(aT1);
            float2 fC0 = __half22float2(aC0);
            float2 fC1 = __half22float2(aC1);
            float2 fev = *(const float2*)(g_FEmb + ti * EMB + lane * 2);
            float acc = (fT0.x + fT1.x) + fev.x * (fC0.x + fC1.x)
                      + (fT0.y + fT1.y) + fev.y * (fC0.y + fC1.y);
            float total = block_reduce_256(acc, sredA);
            if (tid == 0 && tH >= 0.f) {
                float lam = g_BA[ti] + g_FB[ti * NCA + lc] + total;
                partial = -(logf(lam + 1e-16f) + lam);
            }
        }
        // ---- pass B: event i_lo ----
        if (i_lo == 0) {
            if (tid == 0 && tL >= 0.f) {
                float lam = g_SP[ty[0]];
                partial += -(logf(lam + 1e-16f) + lam);
            }
        } else {
            int ti = ty[i_lo];
            int lc = ct[i_lo - 1];
            const uint2* __restrict__ ttb = g_TT2 + (size_t)ti * (NTY * LP) + lane;
            const uint2* __restrict__ tcb = g_TC2 + (size_t)lc * (NCA * LP) + lane;
            __half2 aT0 = hz, aT1 = hz, aC0 = hz, aC1 = hz;
            int s = ch;
            for (; s + 8 < i_lo; s += 16) {
                Ent e0 = sh[s], e1 = sh[s + 8];
                uint2 t0 = __ldg(ttb + e0.ko);
                uint2 c0 = __ldg(tcb + e0.co);
                uint2 t1 = __ldg(ttb + e1.ko);
                uint2 c1 = __ldg(tcb + e1.co);
                __half2 td0 = *(__half2*)&e0.tdL;
                __half2 td1 = *(__half2*)&e1.tdL;
                aT0 = __hfma2(*(__half2*)&t0.x, fast_exp2_h2(__hmul2(*(__half2*)&t0.y, td0)), aT0);
                aC0 = __hfma2(*(__half2*)&c0.x, fast_exp2_h2(__hmul2(*(__half2*)&c0.y, td0)), aC0);
                aT1 = __hfma2(*(__half2*)&t1.x, fast_exp2_h2(__hmul2(*(__half2*)&t1.y, td1)), aT1);
                aC1 = __hfma2(*(__half2*)&c1.x, fast_exp2_h2(__hmul2(*(__half2*)&c1.y, td1)), aC1);
            }
            if (s < i_lo) {
                Ent e0 = sh[s];
                uint2 t0 = __ldg(ttb + e0.ko);
                uint2 c0 = __ldg(tcb + e0.co);
                __half2 td0 = *(__half2*)&e0.tdL;
                aT0 = __hfma2(*(__half2*)&t0.x, fast_exp2_h2(__hmul2(*(__half2*)&t0.y, td0)), aT0);
                aC0 = __hfma2(*(__half2*)&c0.x, fast_exp2_h2(__hmul2(*(__half2*)&c0.y, td0)), aC0);
            }
            float2 fT0 = __half22float2(aT0);
            float2 fT1 = __half22float2(aT1);
            float2 fC0 = __half22float2(aC0);
            float2 fC1 = __half22float2(aC1);
            float2 fev = *(const float2*)(g_FEmb + ti * EMB + lane * 2);
            float acc = (fT0.x + fT1.x) + fev.x * (fC0.x + fC1.x)
                      + (fT0.y + fT1.y) + fev.y * (fC0.y + fC1.y);
            float total = block_reduce_256(acc, sredB);
            if (tid == 0 && tL >= 0.f) {
                float lam = g_BA[ti] + g_FB[ti * NCA + lc] + total;
                partial += -(logf(lam + 1e-16f) + lam);
            }
        }
    } else if (bid < EVP_BLKS + HT_BLKS) {
        // ---- horizon type channel: (b, t) ----
        int idx0 = bid - EVP_BLKS;
        int bb = idx0 / NTY;
        int t = idx0 - bb * NTY;
        float Tf = readT(Tp);
        const float* ts = times + bb * SEQ;
        const int* ty = types + bb * SEQ;
        float tlast = ts[SEQ - 1];
        for (int s = tid; s < SEQ; s += 256) {
            Ent en; en.tdH = td_to_h2(Tf - ts[s]); en.tdL = 0;
            en.ko = ty[s] * LP; en.co = 0;
            sh[s] = en;
        }
        __syncthreads();
        const uint2* __restrict__ ttb = g_TT2 + (size_t)t * (NTY * LP) + lane;
        __half2 a0 = hz, a1 = hz;
        #pragma unroll 2
        for (int s = ch; s < SEQ; s += 16) {
            Ent e0 = sh[s], e1 = sh[s + 8];
            uint2 r0 = __ldg(ttb + e0.ko);
            uint2 r1 = __ldg(ttb + e1.ko);
            a0 = __hfma2(*(__half2*)&r0.x,
                         fast_exp2_h2(__hmul2(*(__half2*)&r0.y, *(__half2*)&e0.tdH)), a0);
            a1 = __hfma2(*(__half2*)&r1.x,
                         fast_exp2_h2(__hmul2(*(__half2*)&r1.y, *(__half2*)&e1.tdH)), a1);
        }
        float2 f0 = __half22float2(a0);
        float2 f1 = __half22float2(a1);
        float total = block_reduce_256((f0.x + f0.y) + (f1.x + f1.y), sredA);
        if (tid == 0) partial = total * (Tf - tlast);
    } else {
        // ---- horizon category channel: b ----
        int bb = bid - EVP_BLKS - HT_BLKS;
        float Tf = readT(Tp);
        const float* ts = times + bb * SEQ;
        const int* ct = cats + bb * SEQ;
        float tlast = ts[SEQ - 1];
        for (int s = tid; s < SEQ; s += 256) {
            Ent en; en.tdH = td_to_h2(Tf - ts[s]); en.tdL = 0;
            en.co = ct[s] * LP; en.ko = 0;
            sh[s] = en;
        }
        __syncthreads();
        int lcL = ct[SEQ - 1];
        const uint2* __restrict__ tcb = g_TC2 + (size_t)lcL * (NCA * LP) + lane;
        __half2 a0 = hz, a1 = hz;
        #pragma unroll 2
        for (int s = ch; s < SEQ; s += 16) {
            Ent e0 = sh[s], e1 = sh[s + 8];
            uint2 r0 = __ldg(tcb + e0.co);
            uint2 r1 = __ldg(tcb + e1.co);
            a0 = __hfma2(*(__half2*)&r0.x,
                         fast_exp2_h2(__hmul2(*(__half2*)&r0.y, *(__half2*)&e0.tdH)), a0);
            a1 = __hfma2(*(__half2*)&r1.x,
                         fast_exp2_h2(__hmul2(*(__half2*)&r1.y, *(__half2*)&e1.tdH)), a1);
        }
        float2 f0 = __half22float2(a0);
        float2 f1 = __half22float2(a1);
        float2 fsum = *(const float2*)(g_Fsum + lane * 2);
        float acc = (f0.x + f1.x) * fsum.x + (f0.y + f1.y) * fsum.y;
        float total = block_reduce_256(acc, sredA);
        if (tid == 0) partial = total * (Tf - tlast);
    }

    // ---- publish partial + grid-completion finalizer ----
    if (tid == 0) {
        g_part[bid] = partial;
        __threadfence();
        unsigned n = atomicAdd(&g_done, 1u);
        sh_last = (n == (unsigned)(MAIN_BLKS - 1)) ? 1 : 0;
        if (sh_last) __threadfence();
    }
    __syncthreads();
    if (sh_last) {
        double v = 0.0;
        for (int idx = tid; idx < MAIN_BLKS; idx += 256) v += (double)g_part[idx];
        #pragma unroll
        for (int o = 16; o; o >>= 1) v += __shfl_down_sync(0xffffffffu, v, o);
        if ((tid & 31) == 0) dred[tid >> 5] = v;
        __syncthreads();
        if (tid == 0) {
            double r = 0.0;
            #pragma unroll
            for (int w = 0; w < 8; w++) r += dred[w];
            float Tf = readT(Tp);
            for (int b2 = 0; b2 < BSZ; b2++) {
                int lcL = cats[b2 * SEQ + SEQ - 1];
                float tlast = times[b2 * SEQ + SEQ - 1];
                float t0 = times[b2 * SEQ];
                r += (double)((g_Sba + g_SFB[lcL]) * (Tf - tlast) + g_I0 * t0);
            }
            out[0] = (float)r;
            g_done = 0u;  // reset for next replay
        }
    }
}

extern "C" void kernel_launch(void* const* d_in, const int* in_sizes, int n_in,
                              void* d_out, int out_size) {
    const float* times = (const float*)d_in[0];
    const int* types = (const int*)d_in[1];
    const int* cats = (const int*)d_in[2];
    const void* Tp = d_in[3];
    const float* type_emb = (const float*)d_in[4];
    const float* cat_emb = (const float*)d_in[5];
    const float* a = (const float*)d_in[6];
    const float* b = (const float*)d_in[7];
    const float* A = (const float*)d_in[8];
    const float* P = (const float*)d_in[9];
    const float* Bm = (const float*)d_in[10];
    const float* Q = (const float*)d_in[11];
    float* out = (float*)d_out;

    k_prep<<<PREP_BLKS, 256>>>(type_emb, cat_emb, a, b, A, P, Bm, Q);
    k_main<<<MAIN_BLKS, 256>>>(times, types, cats, Tp, out);
}